// round 9
// baseline (speedup 1.0000x reference)
#include <cuda_runtime.h>
#include <cstdint>

// Encoding: B=64, C=512, N=784, K=32. x:(B,C,N) f32; out:(B,K,C) f32.
// K1: logits mma tf32 + softmax -> A ([b][n][k], tf32) + wsum. cp.async double-buffer, 2 CTA/SM.
// K2: out = A^T x, tf32 mma, XOR-swizzled smem, double-buffered, fused epilogue.

#define CDIM 512
#define KD 32
#define NPIX 784
#define BDIM 64
#define CH1 9
#define TS 16
#define TILES1 49

#define XS_STRIDE 516
#define XS_BUF 8256              // 16*516 floats
#define K1_SMEM_FLOATS (2*XS_BUF + 544 + 512 + 32 + 32 + 256)

__device__ float g_A[(size_t)BDIM * NPIX * KD];     // 6.4 MB, [b][n][k]
__device__ float g_wsum[BDIM * CH1 * KD];

__device__ __forceinline__ float rtf32(float v) {
    asm("cvt.rna.tf32.f32 %0, %1;" : "=f"(v) : "f"(v));
    return v;
}
__device__ __forceinline__ void mma8(float* d, uint32_t a0, uint32_t a1,
                                     uint32_t a2, uint32_t a3,
                                     uint32_t b0, uint32_t b1) {
    asm volatile(
        "mma.sync.aligned.m16n8k8.row.col.f32.tf32.tf32.f32 "
        "{%0,%1,%2,%3}, {%4,%5,%6,%7}, {%8,%9}, {%0,%1,%2,%3};"
        : "+f"(d[0]), "+f"(d[1]), "+f"(d[2]), "+f"(d[3])
        : "r"(a0), "r"(a1), "r"(a2), "r"(a3), "r"(b0), "r"(b1));
}
__device__ __forceinline__ uint32_t smem_u32(const void* p) {
    uint32_t a;
    asm("{ .reg .u64 t; cvta.to.shared.u64 t, %1; cvt.u32.u64 %0, t; }" : "=r"(a) : "l"(p));
    return a;
}
__device__ __forceinline__ void cpa4(uint32_t sa, const float* g) {
    asm volatile("cp.async.ca.shared.global [%0], [%1], 4;" :: "r"(sa), "l"(g));
}
#define CPA_COMMIT() asm volatile("cp.async.commit_group;" ::: "memory")
#define CPA_WAIT0()  asm volatile("cp.async.wait_group 0;" ::: "memory")
#define BITS(f) __float_as_uint(f)

// =========================== K1: logits + softmax ===========================
__global__ __launch_bounds__(256, 2) void enc_k1(const float* __restrict__ x,
                                                 const float* __restrict__ cw,
                                                 const float* __restrict__ scale) {
    extern __shared__ float sm[];
    float* x_sm   = sm;                      // [2][16*516]
    float* xc_s   = sm + 2 * XS_BUF;         // 16*34
    float* red_s  = xc_s + 544;              // 512
    float* csq_s  = red_s + 512;             // 32
    float* scl_s  = csq_s + 32;              // 32
    float* wsum_s = scl_s + 32;              // 8*32

    const int b = blockIdx.x / CH1, ch = blockIdx.x % CH1;
    const int tile0 = ch * TILES1 / CH1, tile1 = (ch + 1) * TILES1 / CH1;
    const int t = threadIdx.x, w = t >> 5, l = t & 31;
    const int kt = w & 3, h = w >> 2;         // warp = (k-tile, c-half)

    if (t < KD) scl_s[t] = __ldg(&scale[t]);
#pragma unroll
    for (int kk = 0; kk < 4; kk++) {
        int k = 4 * w + kk;
        float s = 0.f;
#pragma unroll
        for (int q = 0; q < 4; q++) {
            float4 v = __ldg((const float4*)&cw[k * CDIM + l * 16 + 4 * q]);
            float e0 = rtf32(v.x), e1 = rtf32(v.y), e2 = rtf32(v.z), e3 = rtf32(v.w);
            s += e0 * e0 + e1 * e1 + e2 * e2 + e3 * e3;
        }
#pragma unroll
        for (int o = 16; o; o >>= 1) s += __shfl_xor_sync(~0u, s, o);
        if (l == 0) csq_s[k] = s;
    }

    // persistent codeword B-fragments (tf32): warp covers k=8kt..+7, c-half h
    uint32_t cwf0[32], cwf1[32];
    const int crow = kt * 8 + (l >> 2), cp = l & 3;
#pragma unroll
    for (int s = 0; s < 32; s++) {
        int c = h * 256 + 8 * s + cp;
        cwf0[s] = BITS(rtf32(__ldg(&cw[crow * CDIM + c])));
        cwf1[s] = BITS(rtf32(__ldg(&cw[crow * CDIM + c + 4])));
    }

    float wsum_acc = 0.f;
    const float* xb = x + (size_t)b * CDIM * NPIX;
    const int nl = t & 15, cb16 = t >> 4;
    const uint32_t xs_addr = smem_u32(x_sm);

#define K1_ISSUE(tile) do { \
        int nn0 = (tile) * TS; \
        uint32_t base = xs_addr + 4u * (((tile) & 1) * XS_BUF + nl * XS_STRIDE); \
        _Pragma("unroll") \
        for (int i = 0; i < 32; i++) { \
            int c = cb16 + 16 * i; \
            cpa4(base + 4u * c, xb + (size_t)c * NPIX + nn0 + nl); \
        } \
        CPA_COMMIT(); \
    } while (0)

    K1_ISSUE(tile0);
    CPA_WAIT0();

    for (int tile = tile0; tile < tile1; tile++) {
        const int n0 = tile * TS;
        const int cur = tile & 1;
        const float* xcur = x_sm + cur * XS_BUF;
        __syncthreads();                       // staged cur visible; nxt buffer free
        if (tile + 1 < tile1) { K1_ISSUE(tile + 1); }

        // phase 1: xc = x . cw^T (x raw fp32 -> HW tf32 truncation)
        float dA[4] = {0.f, 0.f, 0.f, 0.f}, dB[4] = {0.f, 0.f, 0.f, 0.f};
        const int r0 = (l >> 2) * XS_STRIDE, r1 = ((l >> 2) + 8) * XS_STRIDE;
#pragma unroll
        for (int s = 0; s < 32; s++) {
            int c = h * 256 + 8 * s + cp;
            uint32_t a0 = BITS(xcur[r0 + c]);
            uint32_t a1 = BITS(xcur[r1 + c]);
            uint32_t a2 = BITS(xcur[r0 + c + 4]);
            uint32_t a3 = BITS(xcur[r1 + c + 4]);
            mma8((s & 1) ? dB : dA, a0, a1, a2, a3, cwf0[s], cwf1[s]);
        }
        float d4[4];
#pragma unroll
        for (int i = 0; i < 4; i++) d4[i] = dA[i] + dB[i];
        if (h == 1)
            *(float4*)&red_s[(kt * 32 + l) * 4] = make_float4(d4[0], d4[1], d4[2], d4[3]);
        __syncthreads();
        if (h == 0) {
            float4 rr = *(const float4*)&red_s[(kt * 32 + l) * 4];
            d4[0] += rr.x; d4[1] += rr.y; d4[2] += rr.z; d4[3] += rr.w;
            int rrow = l >> 2, cc = kt * 8 + 2 * (l & 3);
            *(float2*)&xc_s[rrow * 34 + cc] = make_float2(d4[0], d4[1]);
            *(float2*)&xc_s[(rrow + 8) * 34 + cc] = make_float2(d4[2], d4[3]);
        }
        __syncthreads();

        // softmax: warp w rows {w, w+8}, lane = k; xsq from smem (fp32 exact)
#pragma unroll
        for (int r = 0; r < 2; r++) {
            int n = w + 8 * r;
            float xs = 0.f;
#pragma unroll
            for (int j = 0; j < 16; j++) {
                float v = xcur[n * XS_STRIDE + l + 32 * j];
                xs = fmaf(v, v, xs);
            }
#pragma unroll
            for (int o = 16; o; o >>= 1) xs += __shfl_xor_sync(~0u, xs, o);
            float xc = xc_s[n * 34 + l];
            float dd = scl_s[l] * (xs - 2.f * xc + csq_s[l]);
            float m = dd;
#pragma unroll
            for (int o = 16; o; o >>= 1) m = fmaxf(m, __shfl_xor_sync(~0u, m, o));
            float e = __expf(dd - m);
            float ss = e;
#pragma unroll
            for (int o = 16; o; o >>= 1) ss += __shfl_xor_sync(~0u, ss, o);
            float a = rtf32(__fdividef(e, ss));
            wsum_acc += a;
            g_A[((size_t)b * NPIX + n0 + n) * KD + l] = a;   // coalesced
        }
        if (tile + 1 < tile1) { CPA_WAIT0(); }
    }

    wsum_s[w * KD + l] = wsum_acc;
    __syncthreads();
    if (t < KD) {
        float s = 0.f;
#pragma unroll
        for (int ww = 0; ww < 8; ww++) s += wsum_s[ww * KD + t];
        g_wsum[(b * CH1 + ch) * KD + t] = s;
    }
}

// ==== K2: out = A^T x, XOR-swizzled smem, double-buffered, fused epilogue ====
__global__ __launch_bounds__(256) void enc_k2(const float* __restrict__ x,
                                              const float* __restrict__ cw,
                                              float* __restrict__ out) {
    const int b = blockIdx.x >> 3, cb = blockIdx.x & 7;   // cb: 64-c block
    const int t = threadIdx.x, w = t >> 5, l = t & 31;
    const int mt = w & 1, cq = w >> 1;   // warp = (k-half 16, c-quarter 16)

    __shared__ float A_s[2][32 * 32];    // [n][k], granule-swizzled
    __shared__ float x_s[2][64 * 32];    // [c][n], granule-swizzled
    __shared__ float wsum_s[KD];

    if (t < KD) {
        float s = 0.f;
#pragma unroll
        for (int ch = 0; ch < CH1; ch++) s += g_wsum[(b * CH1 + ch) * KD + t];
        wsum_s[t] = s;
    }

    float acc[2][4];
#pragma unroll
    for (int i = 0; i < 2; i++)
#pragma unroll
        for (int j = 0; j < 4; j++) acc[i][j] = 0.f;

    const float* xb = x + ((size_t)b * CDIM + cb * 64) * NPIX;
    const float* Ab = g_A + (size_t)b * NPIX * KD;
    const int ar = t >> 3, ak4 = t & 7;   // A staging: n row, k-granule
    const int xc_ = t >> 2, xj = t & 3;   // x staging: c row, n-granule

#define K2_LDG(n0, av, v0, v1) do { \
        av = ((n0) + ar < NPIX) \
            ? __ldg((const float4*)&Ab[(size_t)((n0) + ar) * KD + 4 * ak4]) \
            : make_float4(0.f, 0.f, 0.f, 0.f); \
        v0 = ((n0) + 4 * xj < NPIX) \
            ? __ldg((const float4*)&xb[(size_t)xc_ * NPIX + (n0) + 4 * xj]) \
            : make_float4(0.f, 0.f, 0.f, 0.f); \
        v1 = ((n0) + 4 * (xj + 4) < NPIX) \
            ? __ldg((const float4*)&xb[(size_t)xc_ * NPIX + (n0) + 4 * (xj + 4)]) \
            : make_float4(0.f, 0.f, 0.f, 0.f); \
    } while (0)

#define K2_STS(bi, av, v0, v1) do { \
        *(float4*)&A_s[bi][ar * 32 + 4 * (ak4 ^ (ar & 7))] = av; \
        *(float4*)&x_s[bi][xc_ * 32 + 4 * (xj ^ (xc_ & 7))] = v0; \
        *(float4*)&x_s[bi][xc_ * 32 + 4 * ((xj + 4) ^ (xc_ & 7))] = v1; \
    } while (0)

    {   // prologue: stage tile 0 into buffer 0
        float4 av, v0, v1;
        K2_LDG(0, av, v0, v1);
        K2_STS(0, av, v0, v1);
    }
    __syncthreads();

    const int kg0 = mt * 4 + (l >> 4);         // k granule of k0 = mt*16 + (l>>2)
    const int koff = (l >> 2) & 3;
    const int q3 = l & 3;                      // pn&7 for row pn; (pn+4)&7 = q3+4
    const int cr7 = l >> 2;                    // crow&7

    for (int tl = 0; tl < 25; tl++) {
        const int cur = tl & 1;
        float4 av, v0, v1;
        if (tl < 24) { K2_LDG((tl + 1) * 32, av, v0, v1); }   // overlap with mma

#pragma unroll
        for (int ks = 0; ks < 4; ks++) {
            int pn = 8 * ks + q3;
            uint32_t a0 = BITS(A_s[cur][pn * 32 + 4 * (kg0 ^ q3) + koff]);
            uint32_t a1 = BITS(A_s[cur][pn * 32 + 4 * ((kg0 + 2) ^ q3) + koff]);
            uint32_t a2 = BITS(A_s[cur][(pn + 4) * 32 + 4 * (kg0 ^ (q3 + 4)) + koff]);
            uint32_t a3 = BITS(A_s[cur][(pn + 4) * 32 + 4 * ((kg0 + 2) ^ (q3 + 4)) + koff]);
#pragma unroll
            for (int nt = 0; nt < 2; nt++) {
                int crow = cq * 16 + nt * 8 + cr7;
                uint32_t b0 = BITS(x_s[cur][crow * 32 + 4 * ((2 * ks) ^ cr7) + q3]);
                uint32_t b1 = BITS(x_s[cur][crow * 32 + 4 * ((2 * ks + 1) ^ cr7) + q3]);
                mma8(acc[nt], a0, a1, a2, a3, b0, b1);
            }
        }
        if (tl < 24) { K2_STS(1 - cur, av, v0, v1); }   // write other buffer
        __syncthreads();
    }

    // fused epilogue: out = acc - wsum*cw
    const int k0 = mt * 16 + (l >> 2);
#pragma unroll
    for (int nt = 0; nt < 2; nt++) {
        int c = cb * 64 + cq * 16 + nt * 8 + 2 * (l & 3);
#pragma unroll
        for (int half = 0; half < 2; half++) {
            int k = k0 + 8 * half;
            float2 cv = __ldg((const float2*)&cw[k * CDIM + c]);
            float ws = wsum_s[k];
            float2 o;
            o.x = acc[nt][2 * half]     - ws * cv.x;
            o.y = acc[nt][2 * half + 1] - ws * cv.y;
            *(float2*)&out[((size_t)b * KD + k) * CDIM + c] = o;
        }
    }
}

extern "C" void kernel_launch(void* const* d_in, const int* in_sizes, int n_in,
                              void* d_out, int out_size) {
    const float* x     = (const float*)d_in[0];
    const float* cw    = (const float*)d_in[1];
    const float* scale = (const float*)d_in[2];
    static int configured = 0;
    if (!configured) {
        cudaFuncSetAttribute(enc_k1, cudaFuncAttributeMaxDynamicSharedMemorySize,
                             K1_SMEM_FLOATS * 4);
        configured = 1;
    }
    enc_k1<<<BDIM * CH1, 256, K1_SMEM_FLOATS * 4>>>(x, cw, scale);
    enc_k2<<<BDIM * 8, 256>>>(x, cw, (float*)d_out);
}

// round 10
// speedup vs baseline: 1.1683x; 1.1683x over previous
#include <cuda_runtime.h>
#include <cstdint>

// Encoding: B=64, C=512, N=784, K=32. x:(B,C,N) f32; out:(B,K,C) f32.
// K1: logits mma tf32 + softmax -> A ([b][n][k], tf32) + wsum. Register-prefetched staging.
// K2: out = A^T x, tf32 mma, double-buffered, conflict-free blocked x layout, fused epilogue.

#define CDIM 512
#define KD 32
#define NPIX 784
#define BDIM 64
#define CH1 9
#define TS 16
#define TILES1 49

__device__ float g_A[(size_t)BDIM * NPIX * KD];     // 6.4 MB, [b][n][k]
__device__ float g_wsum[BDIM * CH1 * KD];

__device__ __forceinline__ float rtf32(float v) {
    asm("cvt.rna.tf32.f32 %0, %1;" : "=f"(v) : "f"(v));
    return v;
}
__device__ __forceinline__ void mma8(float* d, uint32_t a0, uint32_t a1,
                                     uint32_t a2, uint32_t a3,
                                     uint32_t b0, uint32_t b1) {
    asm volatile(
        "mma.sync.aligned.m16n8k8.row.col.f32.tf32.tf32.f32 "
        "{%0,%1,%2,%3}, {%4,%5,%6,%7}, {%8,%9}, {%0,%1,%2,%3};"
        : "+f"(d[0]), "+f"(d[1]), "+f"(d[2]), "+f"(d[3])
        : "r"(a0), "r"(a1), "r"(a2), "r"(a3), "r"(b0), "r"(b1));
}
#define BITS(f) __float_as_uint(f)

// =========================== K1: logits + softmax ===========================
__global__ __launch_bounds__(256) void enc_k1(const float* __restrict__ x,
                                              const float* __restrict__ cw,
                                              const float* __restrict__ scale) {
    const int b = blockIdx.x / CH1, ch = blockIdx.x % CH1;
    const int tile0 = ch * TILES1 / CH1, tile1 = (ch + 1) * TILES1 / CH1;
    const int t = threadIdx.x, w = t >> 5, l = t & 31;
    const int kt = w & 3, h = w >> 2;         // warp = (k-tile, c-half)

    __shared__ float x_s[TS * 516];
    __shared__ float xc_s[TS * 34];
    __shared__ float red_s[4 * 32 * 4];
    __shared__ float part_s[TS * 17];
    __shared__ float csq_s[KD], scl_s[KD];
    __shared__ float wsum_s[8][KD];

    if (t < KD) scl_s[t] = __ldg(&scale[t]);
#pragma unroll
    for (int kk = 0; kk < 4; kk++) {
        int k = 4 * w + kk;
        float s = 0.f;
#pragma unroll
        for (int q = 0; q < 4; q++) {
            float4 v = __ldg((const float4*)&cw[k * CDIM + l * 16 + 4 * q]);
            float e0 = rtf32(v.x), e1 = rtf32(v.y), e2 = rtf32(v.z), e3 = rtf32(v.w);
            s += e0 * e0 + e1 * e1 + e2 * e2 + e3 * e3;
        }
#pragma unroll
        for (int o = 16; o; o >>= 1) s += __shfl_xor_sync(~0u, s, o);
        if (l == 0) csq_s[k] = s;
    }

    // persistent codeword B-fragments (tf32): warp covers k=8kt..+7, c-half h
    uint32_t cwf0[32], cwf1[32];
    const int crow = kt * 8 + (l >> 2), cp = l & 3;
#pragma unroll
    for (int s = 0; s < 32; s++) {
        int c = h * 256 + 8 * s + cp;
        cwf0[s] = BITS(rtf32(__ldg(&cw[crow * CDIM + c])));
        cwf1[s] = BITS(rtf32(__ldg(&cw[crow * CDIM + c + 4])));
    }

    float wsum_acc = 0.f;
    const float* xb = x + (size_t)b * CDIM * NPIX;
    const int nl = t & 15, cb16 = t >> 4;

    float buf[32];
#define LDREG(n0) _Pragma("unroll") \
    for (int i = 0; i < 32; i++) buf[i] = __ldg(&xb[(cb16 + 16 * i) * NPIX + (n0) + nl]);

    LDREG(tile0 * TS);
    for (int tile = tile0; tile < tile1; tile++) {
        const int n0 = tile * TS;
        __syncthreads();
        // commit prefetched tile (tf32) + xsq partial
        float xsqp = 0.f;
#pragma unroll
        for (int i = 0; i < 32; i++) {
            float v = rtf32(buf[i]);
            x_s[nl * 516 + cb16 + 16 * i] = v;
            xsqp = fmaf(v, v, xsqp);
        }
        part_s[nl * 17 + cb16] = xsqp;
        __syncthreads();
        if (tile + 1 < tile1) { LDREG(n0 + TS); }   // overlap next-tile DRAM latency

        // phase 1: xc = x . cw^T, 32 k-steps, 2 accumulation chains
        float dA[4] = {0.f, 0.f, 0.f, 0.f}, dB[4] = {0.f, 0.f, 0.f, 0.f};
        const int r0 = (l >> 2) * 516, r1 = ((l >> 2) + 8) * 516;
#pragma unroll
        for (int s = 0; s < 32; s++) {
            int c = h * 256 + 8 * s + cp;
            uint32_t a0 = BITS(x_s[r0 + c]);
            uint32_t a1 = BITS(x_s[r1 + c]);
            uint32_t a2 = BITS(x_s[r0 + c + 4]);
            uint32_t a3 = BITS(x_s[r1 + c + 4]);
            mma8((s & 1) ? dB : dA, a0, a1, a2, a3, cwf0[s], cwf1[s]);
        }
        float d4[4];
#pragma unroll
        for (int i = 0; i < 4; i++) d4[i] = dA[i] + dB[i];
        if (h == 1)
            *(float4*)&red_s[(kt * 32 + l) * 4] = make_float4(d4[0], d4[1], d4[2], d4[3]);
        __syncthreads();
        if (h == 0) {
            float4 rr = *(const float4*)&red_s[(kt * 32 + l) * 4];
            d4[0] += rr.x; d4[1] += rr.y; d4[2] += rr.z; d4[3] += rr.w;
            int rrow = l >> 2, cc = kt * 8 + 2 * (l & 3);
            *(float2*)&xc_s[rrow * 34 + cc] = make_float2(d4[0], d4[1]);
            *(float2*)&xc_s[(rrow + 8) * 34 + cc] = make_float2(d4[2], d4[3]);
        }
        __syncthreads();

        // softmax: warp w rows {w, w+8}, lane = k
#pragma unroll
        for (int r = 0; r < 2; r++) {
            int n = w + 8 * r;
            float xs = 0.f;
#pragma unroll
            for (int q = 0; q < 16; q++) xs += part_s[n * 17 + q];
            float xc = xc_s[n * 34 + l];
            float dd = scl_s[l] * (xs - 2.f * xc + csq_s[l]);
            float m = dd;
#pragma unroll
            for (int o = 16; o; o >>= 1) m = fmaxf(m, __shfl_xor_sync(~0u, m, o));
            float e = __expf(dd - m);
            float ss = e;
#pragma unroll
            for (int o = 16; o; o >>= 1) ss += __shfl_xor_sync(~0u, ss, o);
            float a = rtf32(__fdividef(e, ss));
            wsum_acc += a;
            g_A[((size_t)b * NPIX + n0 + n) * KD + l] = a;   // coalesced
        }
    }

    wsum_s[w][l] = wsum_acc;
    __syncthreads();
    if (t < KD) {
        float s = 0.f;
#pragma unroll
        for (int ww = 0; ww < 8; ww++) s += wsum_s[ww][t];
        g_wsum[(b * CH1 + ch) * KD + t] = s;
    }
}

// ==== K2: out = A^T x, double-buffered, blocked conflict-free x_s, fused epilogue ====
// x_s layout: n-group j (=n/4, 0..7) major, stride 66 float4; element (j, c, n%4)
//   at float offset (j*66 + c)*4 + (n%4).  STS.128 and fragment LDS both bank-clean.
__global__ __launch_bounds__(256) void enc_k2(const float* __restrict__ x,
                                              const float* __restrict__ cw,
                                              float* __restrict__ out) {
    const int b = blockIdx.x >> 3, cb = blockIdx.x & 7;   // cb: 64-c block
    const int t = threadIdx.x, w = t >> 5, l = t & 31;
    const int mt = w & 1, cq = w >> 1;   // warp = (k-half 16, c-quarter 16)

    __shared__ float A_s[2][32 * 40];      // [32n][32k], stride 40
    __shared__ float x_s[2][8 * 66 * 4];   // blocked, 2112 floats/buf
    __shared__ float wsum_s[KD];

    if (t < KD) {
        float s = 0.f;
#pragma unroll
        for (int ch = 0; ch < CH1; ch++) s += g_wsum[(b * CH1 + ch) * KD + t];
        wsum_s[t] = s;
    }

    float acc[2][4];
#pragma unroll
    for (int i = 0; i < 2; i++)
#pragma unroll
        for (int j = 0; j < 4; j++) acc[i][j] = 0.f;

    const float* xb = x + ((size_t)b * CDIM + cb * 64) * NPIX;
    const float* Ab = g_A + (size_t)b * NPIX * KD;
    const int ar = t >> 3, ak4 = t & 7;   // A staging: n row, k-float4
    const int xc_ = t >> 2, xj = t & 3;   // x staging: c row, n-group (and +4)

#define K2_LDG(n0, av, v0, v1) do { \
        av = ((n0) + ar < NPIX) \
            ? __ldg((const float4*)&Ab[(size_t)((n0) + ar) * KD + 4 * ak4]) \
            : make_float4(0.f, 0.f, 0.f, 0.f); \
        v0 = ((n0) + 4 * xj < NPIX) \
            ? __ldg((const float4*)&xb[(size_t)xc_ * NPIX + (n0) + 4 * xj]) \
            : make_float4(0.f, 0.f, 0.f, 0.f); \
        v1 = ((n0) + 4 * (xj + 4) < NPIX) \
            ? __ldg((const float4*)&xb[(size_t)xc_ * NPIX + (n0) + 4 * (xj + 4)]) \
            : make_float4(0.f, 0.f, 0.f, 0.f); \
    } while (0)

    // raw fp32 stores: HMMA.TF32 truncates in HW, no cvt needed
#define K2_STS(bi, av, v0, v1) do { \
        *(float4*)&A_s[bi][ar * 40 + 4 * ak4] = av; \
        *(float4*)&x_s[bi][(xj * 66 + xc_) * 4] = v0; \
        *(float4*)&x_s[bi][((xj + 4) * 66 + xc_) * 4] = v1; \
    } while (0)

    {   // prologue: stage tile 0 into buffer 0
        float4 av, v0, v1;
        K2_LDG(0, av, v0, v1);
        K2_STS(0, av, v0, v1);
    }
    __syncthreads();

    const int q3 = l & 3, c7 = l >> 2;

    for (int tl = 0; tl < 25; tl++) {
        const int cur = tl & 1;
        float4 av, v0, v1;
        if (tl < 24) { K2_LDG((tl + 1) * 32, av, v0, v1); }   // overlap with mma

#pragma unroll
        for (int ks = 0; ks < 4; ks++) {
            int pn = 8 * ks + q3;
            uint32_t a0 = BITS(A_s[cur][pn * 40 + mt * 16 + c7]);
            uint32_t a1 = BITS(A_s[cur][pn * 40 + mt * 16 + c7 + 8]);
            uint32_t a2 = BITS(A_s[cur][(pn + 4) * 40 + mt * 16 + c7]);
            uint32_t a3 = BITS(A_s[cur][(pn + 4) * 40 + mt * 16 + c7 + 8]);
#pragma unroll
            for (int nt = 0; nt < 2; nt++) {
                int crow = cq * 16 + nt * 8 + c7;
                uint32_t b0 = BITS(x_s[cur][((2 * ks) * 66 + crow) * 4 + q3]);
                uint32_t b1 = BITS(x_s[cur][((2 * ks + 1) * 66 + crow) * 4 + q3]);
                mma8(acc[nt], a0, a1, a2, a3, b0, b1);
            }
        }
        if (tl < 24) { K2_STS(1 - cur, av, v0, v1); }   // write other buffer
        __syncthreads();
    }

    // fused epilogue: out = acc - wsum*cw
    const int k0 = mt * 16 + c7;
#pragma unroll
    for (int nt = 0; nt < 2; nt++) {
        int c = cb * 64 + cq * 16 + nt * 8 + 2 * q3;
#pragma unroll
        for (int half = 0; half < 2; half++) {
            int k = k0 + 8 * half;
            float2 cv = __ldg((const float2*)&cw[k * CDIM + c]);
            float ws = wsum_s[k];
            float2 o;
            o.x = acc[nt][2 * half]     - ws * cv.x;
            o.y = acc[nt][2 * half + 1] - ws * cv.y;
            *(float2*)&out[((size_t)b * KD + k) * CDIM + c] = o;
        }
    }
}

extern "C" void kernel_launch(void* const* d_in, const int* in_sizes, int n_in,
                              void* d_out, int out_size) {
    const float* x     = (const float*)d_in[0];
    const float* cw    = (const float*)d_in[1];
    const float* scale = (const float*)d_in[2];
    enc_k1<<<BDIM * CH1, 256>>>(x, cw, scale);
    enc_k2<<<BDIM * 8, 256>>>(x, cw, (float*)d_out);
}